// round 4
// baseline (speedup 1.0000x reference)
#include <cuda_runtime.h>
#include <cstdint>
#include <math.h>

#define N_PRIORS 268800
#define MAXK 750
#define CAP 2048          // candidate capacity (score > CTHR)
#define M1 1024           // sorted prefix length for bitmask NMS
#define W1 (M1 / 64)      // 16 u64 words per mask row
#define CTHR 0.995f
#define NSUPW ((N_PRIORS + 31) / 32)
#define PF 16             // scan prefetch depth

// ---------------- static device scratch (no allocations allowed) ----------------
__device__ float4 g_boxes[N_PRIORS];                    // decoded boxes, pixel coords
__device__ float  g_area[N_PRIORS];                     // (+1 convention) areas
__device__ unsigned long long g_ckeys[CAP];             // candidate keys (unordered)
__device__ int    g_cnt;                                // candidate count (reset at tail; init 0)
__device__ int    g_ncand;
__device__ int    g_overflow;
__device__ int    g_sorder[CAP];                        // sorted original indices (desc, stable)
__device__ float4 g_sbox[M1];
__device__ float  g_sarea[M1];
__device__ unsigned long long g_mask[(size_t)M1 * W1];  // row i: bits j (j>i) that i suppresses
__device__ int    g_kept_idx[MAXK];
__device__ int    g_state[2];                           // [0]=kept, [1]=done
__device__ unsigned int g_supp[NSUPW];                  // fallback suppression bitmap

// ---------------- priors, pure f32 (bit-identical to numpy f64 -> f32 path) ------
// (x+0.5)*step/2560 == (2x+1)/D with D in {640,320,160}; both operands exact in
// f32 and the quotient is never close enough to an f32 midpoint for double
// rounding to differ -> single f32 IEEE divide matches the reference bits.
__device__ __forceinline__ void get_prior(int i, float& px, float& py, float& ps) {
    int r, f; float D, ps0, ps1;
    if (i < 204800)      { r = i;          f = 320; D = 640.0f;
                           ps0 = (float)(16.0  / 2560.0); ps1 = (float)(32.0  / 2560.0); }
    else if (i < 256000) { r = i - 204800; f = 160; D = 320.0f;
                           ps0 = (float)(64.0  / 2560.0); ps1 = (float)(128.0 / 2560.0); }
    else                 { r = i - 256000; f = 80;  D = 160.0f;
                           ps0 = (float)(256.0 / 2560.0); ps1 = (float)(512.0 / 2560.0); }
    int c = r >> 1;
    int x = c % f;
    int y = c / f;
    px = (float)(2 * x + 1) / D;     // IEEE f32 divide
    py = (float)(2 * y + 1) / D;
    ps = (r & 1) ? ps1 : ps0;
}

// IoU with +1 area convention; op order mirrors the reference exactly.
// (bi, ai) = KEPT box, (bj, aj) = candidate  (matches area[idx] + area - inter).
__device__ __forceinline__ bool iou_gt(const float4 bi, const float ai,
                                       const float4 bj, const float aj) {
    float xx1 = fmaxf(bi.x, bj.x);
    float yy1 = fmaxf(bi.y, bj.y);
    float xx2 = fminf(bi.z, bj.z);
    float yy2 = fminf(bi.w, bj.w);
    float iw = fmaxf(0.0f, __fadd_rn(__fsub_rn(xx2, xx1), 1.0f));
    float ih = fmaxf(0.0f, __fadd_rn(__fsub_rn(yy2, yy1), 1.0f));
    float inter = __fmul_rn(iw, ih);
    float uni = __fsub_rn(__fadd_rn(ai, aj), inter);
    float iou = inter / uni;          // IEEE divide
    return iou > 0.4f;
}

// ---------------- decode all boxes + candidate selection ----------------
__global__ void decode_kernel(const float* __restrict__ loc,
                              const float* __restrict__ scores) {
    int i = blockIdx.x * blockDim.x + threadIdx.x;
    if (i >= N_PRIORS) return;

    float px, py, ps;
    get_prior(i, px, py, ps);

    float4 l = reinterpret_cast<const float4*>(loc)[i];

    float cx = __fadd_rn(px, __fmul_rn(__fmul_rn(l.x, 0.1f), ps));
    float cy = __fadd_rn(py, __fmul_rn(__fmul_rn(l.y, 0.1f), ps));
    float w = __fmul_rn(ps, expf(__fmul_rn(l.z, 0.2f)));
    float h = __fmul_rn(ps, expf(__fmul_rn(l.w, 0.2f)));

    float x1 = __fmul_rn(__fsub_rn(cx, __fmul_rn(w, 0.5f)), 2560.0f);
    float y1 = __fmul_rn(__fsub_rn(cy, __fmul_rn(h, 0.5f)), 2560.0f);
    float x2 = __fmul_rn(__fadd_rn(cx, __fmul_rn(w, 0.5f)), 2560.0f);
    float y2 = __fmul_rn(__fadd_rn(cy, __fmul_rn(h, 0.5f)), 2560.0f);

    g_boxes[i] = make_float4(x1, y1, x2, y2);
    g_area[i] = __fmul_rn(__fadd_rn(__fsub_rn(x2, x1), 1.0f),
                          __fadd_rn(__fsub_rn(y2, y1), 1.0f));

    float sc = scores[i];
    if (sc > CTHR) {
        int p = atomicAdd(&g_cnt, 1);
        if (p < CAP) {
            // descending score bits; ties -> ascending index (matches stable argsort)
            g_ckeys[p] = ((unsigned long long)__float_as_uint(sc) << 32)
                       | (unsigned long long)(0xFFFFFFFFu - (unsigned)i);
        }
    }
}

// ---------------- O(n^2) rank sort: 8 blocks x 256, unique keys ----------------
__global__ void rank_kernel() {
    __shared__ unsigned long long sk[CAP];   // 16 KB
    int tid = threadIdx.x;
    int cnt = g_cnt;
    int n = cnt < CAP ? cnt : CAP;

    for (int t = tid; t < CAP; t += 256)
        sk[t] = (t < n) ? g_ckeys[t] : 0ULL;   // pad keys rank below all real keys
    __syncthreads();

    int t = blockIdx.x * 256 + tid;
    if (t < n) {
        unsigned long long k = sk[t];
        int rank = 0;
        #pragma unroll 8
        for (int j = 0; j < CAP; j++)
            rank += (sk[j] > k) ? 1 : 0;
        int idx = (int)(0xFFFFFFFFu - (unsigned)(k & 0xFFFFFFFFull));
        g_sorder[rank] = idx;
        if (rank < M1) {
            g_sbox[rank] = g_boxes[idx];
            g_sarea[rank] = g_area[idx];
        }
    }
    if (blockIdx.x == 0 && tid == 0) {
        g_ncand = n;
        g_overflow = (cnt > CAP) ? 1 : 0;
    }
}

// ---------------- triangular suppression mask (warp-broadcast j loads) ----------
__global__ void mask_kernel() {
    int t = blockIdx.x * blockDim.x + threadIdx.x;   // M1*W1 = 16384 threads
    int i = t & (M1 - 1);          // consecutive lanes -> consecutive i (coalesced bi)
    int w = t >> 10;               // whole warp shares w -> g_sbox[j] broadcasts
    int jbase = w * 64;
    int n1 = g_ncand < M1 ? g_ncand : M1;

    unsigned long long bits = 0ULL;
    if (i < n1 && jbase + 63 > i) {
        float4 bi = g_sbox[i];
        float ai = g_sarea[i];
        int jj0 = (i + 1 > jbase) ? (i + 1 - jbase) : 0;
        int jjend = (jbase + 64 <= n1) ? 64 : (n1 - jbase);
        #pragma unroll 4
        for (int jj = jj0; jj < jjend; jj++) {
            int j = jbase + jj;
            if (iou_gt(bi, ai, g_sbox[j], g_sarea[j])) bits |= (1ULL << jj);
        }
    }
    g_mask[(size_t)i * W1 + w] = bits;
}

// ---------------- single-warp greedy bit-scan, shfl-free inner loop -------------
__global__ void scan_kernel() {
    int lane = threadIdx.x;            // lanes 0..W1-1 own rem word `lane`
    int ncand = g_ncand;
    int n1 = ncand < M1 ? ncand : M1;

    unsigned long long rem = 0ULL;     // this lane's aggregated suppression word
    unsigned long long cur = 0ULL;     // replicated current decision word
    unsigned long long bdist[PF], bself[PF];

    #pragma unroll
    for (int q = 0; q < PF; q++) {
        bdist[q] = (lane < W1 && q < n1) ? g_mask[(size_t)q * W1 + lane] : 0ULL;
        bself[q] = (q < n1) ? g_mask[(size_t)q * W1 + (q >> 6)] : 0ULL;
    }

    int kept = 0;
    for (int p = 0; p < n1; p++) {
        int slot = p & (PF - 1);
        unsigned long long rd = bdist[slot];
        unsigned long long rs = bself[slot];
        int pf = p + PF;
        if (pf < n1) {
            bdist[slot] = (lane < W1) ? g_mask[(size_t)pf * W1 + lane] : 0ULL;
            bself[slot] = g_mask[(size_t)pf * W1 + (pf >> 6)];   // broadcast load
        }
        if ((p & 63) == 0 && p)
            cur = __shfl_sync(0xffffffffu, rem, p >> 6);
        if (!((cur >> (p & 63)) & 1ULL)) {
            if (lane == 0) g_kept_idx[kept] = g_sorder[p];
            cur |= rs;       // uniform across warp (same loaded value)
            rem |= rd;       // lane-distributed future words
            kept++;
            if (kept == MAXK) break;
        }
    }

    // continuation over remaining sorted candidates (rarely needed)
    if (kept < MAXK && ncand > M1) {
        __syncwarp();
        __threadfence_block();
        for (int p = M1; p < ncand && kept < MAXK; p++) {
            int orig = g_sorder[p];
            float4 bj = g_boxes[orig];
            float aj = g_area[orig];
            bool hit = false;
            for (int tt = lane; tt < kept; tt += 32) {
                int k = g_kept_idx[tt];
                if (iou_gt(g_boxes[k], g_area[k], bj, aj)) hit = true;
            }
            if (__ballot_sync(0xffffffffu, hit) == 0u) {
                if (lane == 0) g_kept_idx[kept] = orig;
                kept++;
                __syncwarp();
                __threadfence_block();
            }
        }
    }

    if (lane == 0) {
        g_state[0] = kept;
        g_state[1] = (kept >= MAXK && !g_overflow) ? 1 : 0;   // provably complete
    }
}

// ---------------- fallback (expected no-op) + finalize + tail reset -------------
__global__ void __launch_bounds__(1024, 1)
final_kernel(const float* __restrict__ scores,
             const float* __restrict__ landms,
             const float* __restrict__ thrp,
             float* __restrict__ out) {
    __shared__ float rs_[1024];
    __shared__ int   ri_[1024];
    int tid = threadIdx.x;

    if (!g_state[1]) {
        // full reference-style greedy NMS over all priors (guaranteed correct)
        for (int w = tid; w < NSUPW; w += 1024) g_supp[w] = 0u;
        __syncthreads();

        int kept = 0;
        for (int it = 0; it < MAXK; it++) {
            float bs = -1.0f; int bi = 0x7FFFFFFF;
            for (int i = tid; i < N_PRIORS; i += 1024) {
                if (!((g_supp[i >> 5] >> (i & 31)) & 1u)) {
                    float s = scores[i];
                    if (s > bs || (s == bs && i < bi)) { bs = s; bi = i; }
                }
            }
            rs_[tid] = bs; ri_[tid] = bi;
            __syncthreads();
            for (int off = 512; off > 0; off >>= 1) {
                if (tid < off) {
                    float so = rs_[tid + off]; int io = ri_[tid + off];
                    if (so > rs_[tid] || (so == rs_[tid] && io < ri_[tid])) {
                        rs_[tid] = so; ri_[tid] = io;
                    }
                }
                __syncthreads();
            }
            float topS = rs_[0]; int top = ri_[0];
            __syncthreads();
            if (topS < 0.0f) break;

            if (tid == 0) g_kept_idx[kept] = top;
            kept++;

            float4 bt = g_boxes[top];
            float at = g_area[top];
            for (int i = tid; i < N_PRIORS; i += 1024) {
                if (iou_gt(bt, at, g_boxes[i], g_area[i]))
                    atomicOr(&g_supp[i >> 5], 1u << (i & 31));
            }
            __syncthreads();
        }
        if (tid == 0) g_state[0] = kept;
        __syncthreads();
    }

    // ---- finalize: threshold + gather boxes/scores/landmarks ----
    int kept = g_state[0];
    float thr = thrp[0];

    if (tid < MAXK) {
        int i = tid;
        float* ob = out;                 // [750,4]
        float* os = out + MAXK * 4;      // [750]
        float* ol = out + MAXK * 5;      // [750,10]

        float4 b = make_float4(0.f, 0.f, 0.f, 0.f);
        float s = 0.f;
        float lm[10];
        #pragma unroll
        for (int j = 0; j < 10; j++) lm[j] = 0.f;

        if (i < kept) {
            int k = g_kept_idx[i];
            float sc = scores[k];
            if (sc > thr) {
                b = g_boxes[k];
                s = sc;
                float px, py, ps;
                get_prior(k, px, py, ps);
                #pragma unroll
                for (int j = 0; j < 5; j++) {
                    float ox = landms[10 * k + 2 * j + 0];
                    float oy = landms[10 * k + 2 * j + 1];
                    lm[2 * j + 0] = __fmul_rn(__fadd_rn(px, __fmul_rn(__fmul_rn(ox, 0.1f), ps)), 2560.0f);
                    lm[2 * j + 1] = __fmul_rn(__fadd_rn(py, __fmul_rn(__fmul_rn(oy, 0.1f), ps)), 2560.0f);
                }
            }
        }
        ob[4 * i + 0] = b.x;
        ob[4 * i + 1] = b.y;
        ob[4 * i + 2] = b.z;
        ob[4 * i + 3] = b.w;
        os[i] = s;
        #pragma unroll
        for (int j = 0; j < 10; j++) ol[10 * i + j] = lm[j];
    }

    // tail reset for the next (graph-replayed) execution
    __syncthreads();
    if (tid == 0) g_cnt = 0;
}

// ---------------- launch ----------------
extern "C" void kernel_launch(void* const* d_in, const int* in_sizes, int n_in,
                              void* d_out, int out_size) {
    const float* bboxes = (const float*)d_in[0];   // (1, N, 4)
    const float* scores = (const float*)d_in[1];   // (1, N)
    const float* landms = (const float*)d_in[2];   // (1, N, 10)
    const float* thr    = (const float*)d_in[3];   // (1,)
    float* out = (float*)d_out;
    cudaStream_t stream = 0;

    decode_kernel<<<N_PRIORS / 256, 256, 0, stream>>>(bboxes, scores);
    rank_kernel<<<CAP / 256, 256, 0, stream>>>();
    mask_kernel<<<(M1 * W1) / 256, 256, 0, stream>>>();
    scan_kernel<<<1, 32, 0, stream>>>();
    final_kernel<<<1, 1024, 0, stream>>>(scores, landms, thr, out);
}

// round 5
// speedup vs baseline: 1.4004x; 1.4004x over previous
#include <cuda_runtime.h>
#include <cstdint>
#include <math.h>

#define N_PRIORS 268800
#define MAXK 750
#define CAP 2048            // candidate capacity
#define M1 1024             // bitmask NMS width (>= expected ncand)
#define W1 16               // u64 words per mask row (M1/64)
#define CTHR 0.9966f        // E[ncand] ~ 914
#define NSUPW ((N_PRIORS + 31) / 32)
#define NT 1024

// ---------------- static device scratch ----------------
__device__ float4 g_boxes[N_PRIORS];
__device__ unsigned long long g_ckeys[CAP];
__device__ int g_cnt;                       // zero-init; reset at tail of nms kernel
__device__ unsigned int g_supp[NSUPW];      // fallback suppression bitmap

// ---------------- dynamic smem layout ----------------
struct Smem {
    unsigned long long keys[CAP];           // 16 KB
    unsigned long long mask[M1 * W1];       // 128 KB
    float4 sbox[CAP];                       // 32 KB
    float  sarea[CAP];                      // 8 KB
    int    sorder[CAP];                     // 8 KB
    int    keep[MAXK];                      // 3 KB
    int    s_kept, s_done, s_keepmode;
};

// ---------------- priors, pure f32 (bit-identical to numpy f64->f32 path) -------
__device__ __forceinline__ void get_prior(int i, float& px, float& py, float& ps) {
    int r, f; float D, ps0, ps1;
    if (i < 204800)      { r = i;          f = 320; D = 640.0f;
                           ps0 = (float)(16.0  / 2560.0); ps1 = (float)(32.0  / 2560.0); }
    else if (i < 256000) { r = i - 204800; f = 160; D = 320.0f;
                           ps0 = (float)(64.0  / 2560.0); ps1 = (float)(128.0 / 2560.0); }
    else                 { r = i - 256000; f = 80;  D = 160.0f;
                           ps0 = (float)(256.0 / 2560.0); ps1 = (float)(512.0 / 2560.0); }
    int c = r >> 1;
    int x = c % f;
    int y = c / f;
    px = (float)(2 * x + 1) / D;
    py = (float)(2 * y + 1) / D;
    ps = (r & 1) ? ps1 : ps0;
}

// area with reference op order (+1 convention)
__device__ __forceinline__ float box_area(const float4 b) {
    return __fmul_rn(__fadd_rn(__fsub_rn(b.z, b.x), 1.0f),
                     __fadd_rn(__fsub_rn(b.w, b.y), 1.0f));
}

// IoU > 0.4, op order mirrors reference. (bi,ai)=kept, (bj,aj)=candidate.
__device__ __forceinline__ bool iou_gt(const float4 bi, const float ai,
                                       const float4 bj, const float aj) {
    float xx1 = fmaxf(bi.x, bj.x);
    float yy1 = fmaxf(bi.y, bj.y);
    float xx2 = fminf(bi.z, bj.z);
    float yy2 = fminf(bi.w, bj.w);
    float iw = fmaxf(0.0f, __fadd_rn(__fsub_rn(xx2, xx1), 1.0f));
    float ih = fmaxf(0.0f, __fadd_rn(__fsub_rn(yy2, yy1), 1.0f));
    float inter = __fmul_rn(iw, ih);
    float uni = __fsub_rn(__fadd_rn(ai, aj), inter);
    return (inter / uni) > 0.4f;
}

// ---------------- decode all boxes + candidate selection ----------------
__global__ void decode_kernel(const float* __restrict__ loc,
                              const float* __restrict__ scores) {
    int i = blockIdx.x * blockDim.x + threadIdx.x;
    if (i >= N_PRIORS) return;

    float px, py, ps;
    get_prior(i, px, py, ps);

    float4 l = reinterpret_cast<const float4*>(loc)[i];

    float cx = __fadd_rn(px, __fmul_rn(__fmul_rn(l.x, 0.1f), ps));
    float cy = __fadd_rn(py, __fmul_rn(__fmul_rn(l.y, 0.1f), ps));
    float w = __fmul_rn(ps, expf(__fmul_rn(l.z, 0.2f)));
    float h = __fmul_rn(ps, expf(__fmul_rn(l.w, 0.2f)));

    float x1 = __fmul_rn(__fsub_rn(cx, __fmul_rn(w, 0.5f)), 2560.0f);
    float y1 = __fmul_rn(__fsub_rn(cy, __fmul_rn(h, 0.5f)), 2560.0f);
    float x2 = __fmul_rn(__fadd_rn(cx, __fmul_rn(w, 0.5f)), 2560.0f);
    float y2 = __fmul_rn(__fadd_rn(cy, __fmul_rn(h, 0.5f)), 2560.0f);

    g_boxes[i] = make_float4(x1, y1, x2, y2);

    float sc = scores[i];
    if (sc > CTHR) {
        int p = atomicAdd(&g_cnt, 1);
        if (p < CAP) {
            // descending score bits; ties -> ascending index (stable argsort)
            g_ckeys[p] = ((unsigned long long)__float_as_uint(sc) << 32)
                       | (unsigned long long)(0xFFFFFFFFu - (unsigned)i);
        }
    }
}

// ---------------- fused NMS: rank + mask + scan + fallback + finalize ----------
__global__ void __launch_bounds__(NT, 1)
nms_kernel(const float* __restrict__ scores,
           const float* __restrict__ landms,
           const float* __restrict__ thrp,
           float* __restrict__ out) {
    extern __shared__ char smraw[];
    Smem* sm = (Smem*)smraw;
    int tid = threadIdx.x;
    int lane = tid & 31;

    int cnt = g_cnt;                       // all threads read (uniform)
    int n = cnt < CAP ? cnt : CAP;
    int n1 = n < M1 ? n : M1;

    if (tid == 0) { sm->s_keepmode = 0; sm->s_kept = 0; sm->s_done = 0; }

    // ---- load candidate keys ----
    for (int t = tid; t < n; t += NT) sm->keys[t] = g_ckeys[t];
    __syncthreads();

    // ---- O(n^2) rank sort (unique keys -> exact ranks) + gather ----
    for (int t = tid; t < n; t += NT) {
        unsigned long long k = sm->keys[t];
        int rank = 0;
        #pragma unroll 8
        for (int j = 0; j < n; j++) rank += (sm->keys[j] > k) ? 1 : 0;
        int idx = (int)(0xFFFFFFFFu - (unsigned)(k & 0xFFFFFFFFull));
        sm->sorder[rank] = idx;
        float4 b = g_boxes[idx];
        sm->sbox[rank] = b;
        sm->sarea[rank] = box_area(b);
    }
    __syncthreads();

    // ---- triangular suppression mask into smem (row i = thread tid) ----
    {
        int i = tid;                        // M1 == NT
        if (i < n1) {
            float4 bi = sm->sbox[i];
            float ai = sm->sarea[i];
            #pragma unroll
            for (int w = 0; w < W1; w++) {
                unsigned long long bits = 0ULL;
                int jbase = w * 64;
                if (jbase + 63 > i) {
                    int jj0 = (i + 1 > jbase) ? (i + 1 - jbase) : 0;
                    int jjend = (jbase + 64 <= n1) ? 64 : (n1 - jbase);
                    #pragma unroll 4
                    for (int jj = jj0; jj < jjend; jj++) {
                        int j = jbase + jj;
                        if (iou_gt(bi, ai, sm->sbox[j], sm->sarea[j]))
                            bits |= (1ULL << jj);
                    }
                }
                sm->mask[i * W1 + w] = bits;
            }
        } else {
            #pragma unroll
            for (int w = 0; w < W1; w++) sm->mask[i * W1 + w] = 0ULL;
        }
    }
    __syncthreads();

    // ---- single-warp greedy bit-scan, pure-ALU critical path ----
    if (tid < 32) {
        unsigned long long rem = 0ULL;     // lane (lane&15) owns rem word (lane&15)
        int myw = lane & 15;
        int kept = 0;

        for (int p0 = 0; p0 < n1; p0 += 64) {
            int w0 = p0 >> 6;
            unsigned long long cur = __shfl_sync(0xffffffffu, rem, w0);
            // preload the 64 diagonal self-words of this stripe across lanes
            unsigned long long rsA = sm->mask[(p0 + lane) * W1 + w0];
            unsigned long long rsB = sm->mask[(p0 + 32 + lane) * W1 + w0];
            #pragma unroll
            for (int u = 0; u < 64; u++) {
                unsigned long long rs =
                    __shfl_sync(0xffffffffu, (u < 32) ? rsA : rsB, u & 31);
                int p = p0 + u;
                bool take = (p < n1) && (kept < MAXK) && !((cur >> u) & 1ULL);
                if (take) {
                    cur |= rs;                              // uniform
                    rem |= sm->mask[p * W1 + myw];          // off critical path
                    if (lane == 0) sm->keep[kept] = p;      // sorted position
                    kept++;
                }
            }
            if (kept >= MAXK) break;
        }

        // continuation over candidates beyond M1 (structurally ~never runs)
        if (kept < MAXK && n > n1) {
            __syncwarp();
            for (int p = n1; p < n && kept < MAXK; p++) {
                float4 bj = sm->sbox[p];
                float aj = sm->sarea[p];
                bool hit = false;
                for (int t = lane; t < kept; t += 32) {
                    int kp = sm->keep[t];
                    if (iou_gt(sm->sbox[kp], sm->sarea[kp], bj, aj)) hit = true;
                }
                if (__ballot_sync(0xffffffffu, hit) == 0u) {
                    if (lane == 0) sm->keep[kept] = p;
                    kept++;
                    __syncwarp();
                }
            }
        }

        if (lane == 0) {
            sm->s_kept = kept;
            sm->s_done = (kept >= MAXK && cnt <= CAP) ? 1 : 0;
        }
    }
    __syncthreads();

    // ---- guaranteed-correct fallback (expected no-op; uniform branch) ----
    if (!sm->s_done) {
        __shared__ float rs_[NT];
        __shared__ int   ri_[NT];
        for (int w = tid; w < NSUPW; w += NT) g_supp[w] = 0u;
        __syncthreads();

        int kept = 0;
        for (int it = 0; it < MAXK; it++) {
            float bs = -1.0f; int bi = 0x7FFFFFFF;
            for (int i = tid; i < N_PRIORS; i += NT) {
                if (!((g_supp[i >> 5] >> (i & 31)) & 1u)) {
                    float s = scores[i];
                    if (s > bs || (s == bs && i < bi)) { bs = s; bi = i; }
                }
            }
            rs_[tid] = bs; ri_[tid] = bi;
            __syncthreads();
            for (int off = 512; off > 0; off >>= 1) {
                if (tid < off) {
                    float so = rs_[tid + off]; int io = ri_[tid + off];
                    if (so > rs_[tid] || (so == rs_[tid] && io < ri_[tid])) {
                        rs_[tid] = so; ri_[tid] = io;
                    }
                }
                __syncthreads();
            }
            float topS = rs_[0]; int top = ri_[0];
            __syncthreads();
            if (topS < 0.0f) break;

            if (tid == 0) sm->keep[kept] = top;     // ORIGINAL index
            kept++;

            float4 bt = g_boxes[top];
            float at = box_area(bt);
            for (int i = tid; i < N_PRIORS; i += NT) {
                float4 bx = g_boxes[i];
                if (iou_gt(bt, at, bx, box_area(bx)))
                    atomicOr(&g_supp[i >> 5], 1u << (i & 31));
            }
            __syncthreads();
        }
        if (tid == 0) { sm->s_kept = kept; sm->s_keepmode = 1; }
        __syncthreads();
    }

    // ---- finalize: threshold + gather boxes/scores/landmarks ----
    {
        int kept = sm->s_kept;
        int mode = sm->s_keepmode;
        float thr = thrp[0];

        if (tid < MAXK) {
            int i = tid;
            float* ob = out;                 // [750,4]
            float* os = out + MAXK * 4;      // [750]
            float* ol = out + MAXK * 5;      // [750,10]

            float4 b = make_float4(0.f, 0.f, 0.f, 0.f);
            float s = 0.f;
            float lm[10];
            #pragma unroll
            for (int j = 0; j < 10; j++) lm[j] = 0.f;

            if (i < kept) {
                int orig; float4 bb;
                if (mode == 0) {
                    int pos = sm->keep[i];
                    orig = sm->sorder[pos];
                    bb = sm->sbox[pos];
                } else {
                    orig = sm->keep[i];
                    bb = g_boxes[orig];
                }
                float sc = scores[orig];
                if (sc > thr) {
                    b = bb;
                    s = sc;
                    float px, py, ps;
                    get_prior(orig, px, py, ps);
                    #pragma unroll
                    for (int j = 0; j < 5; j++) {
                        float ox = landms[10 * orig + 2 * j + 0];
                        float oy = landms[10 * orig + 2 * j + 1];
                        lm[2 * j + 0] = __fmul_rn(__fadd_rn(px, __fmul_rn(__fmul_rn(ox, 0.1f), ps)), 2560.0f);
                        lm[2 * j + 1] = __fmul_rn(__fadd_rn(py, __fmul_rn(__fmul_rn(oy, 0.1f), ps)), 2560.0f);
                    }
                }
            }
            ob[4 * i + 0] = b.x;
            ob[4 * i + 1] = b.y;
            ob[4 * i + 2] = b.z;
            ob[4 * i + 3] = b.w;
            os[i] = s;
            #pragma unroll
            for (int j = 0; j < 10; j++) ol[10 * i + j] = lm[j];
        }
    }

    // tail reset for next graph replay
    __syncthreads();
    if (tid == 0) g_cnt = 0;
}

// ---------------- launch ----------------
extern "C" void kernel_launch(void* const* d_in, const int* in_sizes, int n_in,
                              void* d_out, int out_size) {
    const float* bboxes = (const float*)d_in[0];   // (1, N, 4)
    const float* scores = (const float*)d_in[1];   // (1, N)
    const float* landms = (const float*)d_in[2];   // (1, N, 10)
    const float* thr    = (const float*)d_in[3];   // (1,)
    float* out = (float*)d_out;
    cudaStream_t stream = 0;

    static const size_t SMEM_BYTES = sizeof(Smem);
    cudaFuncSetAttribute(nms_kernel,
                         cudaFuncAttributeMaxDynamicSharedMemorySize,
                         (int)SMEM_BYTES);

    decode_kernel<<<N_PRIORS / 256, 256, 0, stream>>>(bboxes, scores);
    nms_kernel<<<1, NT, SMEM_BYTES, stream>>>(scores, landms, thr, out);
}

// round 6
// speedup vs baseline: 5.0882x; 3.6334x over previous
#include <cuda_runtime.h>
#include <cstdint>
#include <math.h>

#define N_PRIORS 268800
#define MAXK 750
#define CAP 2048            // candidate capacity
#define M1 1024             // bitmask NMS width
#define W1 16               // u64 words per mask row (M1/64)
#define CTHR 0.9966f        // E[ncand] ~ 914
#define NSUPW ((N_PRIORS + 31) / 32)

// ---------------- static device scratch ----------------
__device__ float4 g_boxes[N_PRIORS];
__device__ unsigned long long g_ckeys[CAP];
__device__ int    g_cnt;                         // zero-init; reset at tail
__device__ int    g_ncand;
__device__ int    g_overflow;
__device__ int    g_sorder[CAP];                 // sorted original indices
__device__ float4 g_sbox[CAP];
__device__ float  g_sarea[CAP];
__device__ unsigned long long g_mask[M1 * W1];   // row i: bits j (j>i) i suppresses
__device__ unsigned int g_supp[NSUPW];           // fallback bitmap

// ---------------- priors, pure f32 (bit-identical to numpy f64->f32 path) -------
__device__ __forceinline__ void get_prior(int i, float& px, float& py, float& ps) {
    int r, f; float D, ps0, ps1;
    if (i < 204800)      { r = i;          f = 320; D = 640.0f;
                           ps0 = (float)(16.0  / 2560.0); ps1 = (float)(32.0  / 2560.0); }
    else if (i < 256000) { r = i - 204800; f = 160; D = 320.0f;
                           ps0 = (float)(64.0  / 2560.0); ps1 = (float)(128.0 / 2560.0); }
    else                 { r = i - 256000; f = 80;  D = 160.0f;
                           ps0 = (float)(256.0 / 2560.0); ps1 = (float)(512.0 / 2560.0); }
    int c = r >> 1;
    int x = c % f;
    int y = c / f;
    px = (float)(2 * x + 1) / D;
    py = (float)(2 * y + 1) / D;
    ps = (r & 1) ? ps1 : ps0;
}

__device__ __forceinline__ float box_area(const float4 b) {
    return __fmul_rn(__fadd_rn(__fsub_rn(b.z, b.x), 1.0f),
                     __fadd_rn(__fsub_rn(b.w, b.y), 1.0f));
}

// IoU > 0.4, op order mirrors reference. (bi,ai)=kept, (bj,aj)=candidate.
__device__ __forceinline__ bool iou_gt(const float4 bi, const float ai,
                                       const float4 bj, const float aj) {
    float xx1 = fmaxf(bi.x, bj.x);
    float yy1 = fmaxf(bi.y, bj.y);
    float xx2 = fminf(bi.z, bj.z);
    float yy2 = fminf(bi.w, bj.w);
    float iw = fmaxf(0.0f, __fadd_rn(__fsub_rn(xx2, xx1), 1.0f));
    float ih = fmaxf(0.0f, __fadd_rn(__fsub_rn(yy2, yy1), 1.0f));
    float inter = __fmul_rn(iw, ih);
    float uni = __fsub_rn(__fadd_rn(ai, aj), inter);
    return (inter / uni) > 0.4f;       // IEEE divide, like reference
}

// ---------------- decode all boxes + candidate selection ----------------
__global__ void decode_kernel(const float* __restrict__ loc,
                              const float* __restrict__ scores) {
    int i = blockIdx.x * blockDim.x + threadIdx.x;
    if (i >= N_PRIORS) return;

    float px, py, ps;
    get_prior(i, px, py, ps);

    float4 l = reinterpret_cast<const float4*>(loc)[i];

    float cx = __fadd_rn(px, __fmul_rn(__fmul_rn(l.x, 0.1f), ps));
    float cy = __fadd_rn(py, __fmul_rn(__fmul_rn(l.y, 0.1f), ps));
    float w = __fmul_rn(ps, expf(__fmul_rn(l.z, 0.2f)));
    float h = __fmul_rn(ps, expf(__fmul_rn(l.w, 0.2f)));

    float x1 = __fmul_rn(__fsub_rn(cx, __fmul_rn(w, 0.5f)), 2560.0f);
    float y1 = __fmul_rn(__fsub_rn(cy, __fmul_rn(h, 0.5f)), 2560.0f);
    float x2 = __fmul_rn(__fadd_rn(cx, __fmul_rn(w, 0.5f)), 2560.0f);
    float y2 = __fmul_rn(__fadd_rn(cy, __fmul_rn(h, 0.5f)), 2560.0f);

    g_boxes[i] = make_float4(x1, y1, x2, y2);

    float sc = scores[i];
    if (sc > CTHR) {
        int p = atomicAdd(&g_cnt, 1);
        if (p < CAP) {
            // descending score bits; ties -> ascending index (stable argsort)
            g_ckeys[p] = ((unsigned long long)__float_as_uint(sc) << 32)
                       | (unsigned long long)(0xFFFFFFFFu - (unsigned)i);
        }
    }
}

// ---------------- grid-wide O(n^2) rank sort (16 blocks x 128) ----------------
__global__ void rank_kernel() {
    __shared__ unsigned long long sk[CAP];       // 16 KB
    int tid = threadIdx.x;
    int cnt = g_cnt;
    int n = cnt < CAP ? cnt : CAP;

    for (int t = tid; t < n; t += 128) sk[t] = g_ckeys[t];
    __syncthreads();

    int t = blockIdx.x * 128 + tid;
    if (t < n) {
        unsigned long long k = sk[t];
        int rank = 0;
        #pragma unroll 8
        for (int j = 0; j < n; j++) rank += (sk[j] > k) ? 1 : 0;
        int idx = (int)(0xFFFFFFFFu - (unsigned)(k & 0xFFFFFFFFull));
        g_sorder[rank] = idx;
        float4 b = g_boxes[idx];
        g_sbox[rank] = b;
        g_sarea[rank] = box_area(b);
    }
    if (blockIdx.x == 0 && tid == 0) {
        g_ncand = n;
        g_overflow = (cnt > CAP) ? 1 : 0;
    }
}

// ---------------- grid-wide triangular suppression mask (64 blocks x 256) ------
__global__ void mask_kernel() {
    int t = blockIdx.x * blockDim.x + threadIdx.x;   // 16384 threads
    int i = t & (M1 - 1);          // consecutive lanes -> consecutive i
    int w = t >> 10;               // whole warp shares w -> g_sbox[j] broadcasts
    int jbase = w * 64;
    int n = g_ncand;
    int n1 = n < M1 ? n : M1;

    unsigned long long bits = 0ULL;
    if (i < n1 && jbase + 63 > i) {
        float4 bi = g_sbox[i];
        float ai = g_sarea[i];
        int jj0 = (i + 1 > jbase) ? (i + 1 - jbase) : 0;
        int jjend = (jbase + 64 <= n1) ? 64 : (n1 - jbase);
        #pragma unroll 4
        for (int jj = jj0; jj < jjend; jj++) {
            int j = jbase + jj;
            if (iou_gt(bi, ai, g_sbox[j], g_sarea[j])) bits |= (1ULL << jj);
        }
    }
    g_mask[i * W1 + w] = bits;
}

// ---------------- scan (1 warp from smem) + fallback + finalize ----------------
struct ScanSmem {
    unsigned long long mask[M1 * W1];   // 128 KB
    int sorder[CAP];                    // 8 KB
    int keep[MAXK];
    int s_kept, s_done, s_keepmode;
};

__global__ void __launch_bounds__(1024, 1)
scanfin_kernel(const float* __restrict__ scores,
               const float* __restrict__ landms,
               const float* __restrict__ thrp,
               float* __restrict__ out) {
    extern __shared__ char smraw[];
    ScanSmem* sm = (ScanSmem*)smraw;
    int tid = threadIdx.x;
    int lane = tid & 31;

    int cnt = g_cnt;
    int n = cnt < CAP ? cnt : CAP;
    int n1 = n < M1 ? n : M1;

    if (tid == 0) { sm->s_kept = 0; sm->s_done = 0; sm->s_keepmode = 0; }

    // cooperative bulk copy: mask + sorder into smem (coalesced)
    {
        const uint4* src = (const uint4*)g_mask;
        uint4* dst = (uint4*)sm->mask;
        #pragma unroll
        for (int q = 0; q < (M1 * W1 * 8) / (16 * 1024); q++)
            dst[q * 1024 + tid] = src[q * 1024 + tid];
        for (int t = tid; t < n; t += 1024) sm->sorder[t] = g_sorder[t];
    }
    __syncthreads();

    // ---- single-warp greedy bit-scan from smem ----
    if (tid < 32) {
        unsigned long long rem = 0ULL;      // lane (lane&15) owns rem word (lane&15)
        int myw = lane & 15;
        int kept = 0;

        for (int p0 = 0; p0 < n1; p0 += 64) {
            int w0 = p0 >> 6;
            unsigned long long cur = __shfl_sync(0xffffffffu, rem, w0);
            unsigned long long rsA = sm->mask[(p0 + lane) * W1 + w0];
            unsigned long long rsB = sm->mask[(p0 + 32 + lane) * W1 + w0];
            #pragma unroll
            for (int u = 0; u < 64; u++) {
                unsigned long long rs =
                    __shfl_sync(0xffffffffu, (u < 32) ? rsA : rsB, u & 31);
                int p = p0 + u;
                bool take = (p < n1) && (kept < MAXK) && !((cur >> u) & 1ULL);
                if (take) {
                    cur |= rs;                              // warp-uniform
                    rem |= sm->mask[p * W1 + myw];          // off critical path
                    if (lane == 0) sm->keep[kept] = p;      // sorted position
                    kept++;
                }
            }
            if (kept >= MAXK) break;
        }

        // continuation over candidates beyond M1 (structurally ~never runs)
        if (kept < MAXK && n > n1) {
            __syncwarp();
            for (int p = n1; p < n && kept < MAXK; p++) {
                float4 bj = g_sbox[p];
                float aj = g_sarea[p];
                bool hit = false;
                for (int t = lane; t < kept; t += 32) {
                    int kp = sm->keep[t];
                    if (iou_gt(g_sbox[kp], g_sarea[kp], bj, aj)) hit = true;
                }
                if (__ballot_sync(0xffffffffu, hit) == 0u) {
                    if (lane == 0) sm->keep[kept] = p;
                    kept++;
                    __syncwarp();
                }
            }
        }

        if (lane == 0) {
            sm->s_kept = kept;
            sm->s_done = (kept >= MAXK && cnt <= CAP) ? 1 : 0;
        }
    }
    __syncthreads();

    // ---- guaranteed-correct fallback (expected no-op; uniform branch) ----
    if (!sm->s_done) {
        __shared__ float rs_[1024];
        __shared__ int   ri_[1024];
        for (int w = tid; w < NSUPW; w += 1024) g_supp[w] = 0u;
        __syncthreads();

        int kept = 0;
        for (int it = 0; it < MAXK; it++) {
            float bs = -1.0f; int bi = 0x7FFFFFFF;
            for (int i = tid; i < N_PRIORS; i += 1024) {
                if (!((g_supp[i >> 5] >> (i & 31)) & 1u)) {
                    float s = scores[i];
                    if (s > bs || (s == bs && i < bi)) { bs = s; bi = i; }
                }
            }
            rs_[tid] = bs; ri_[tid] = bi;
            __syncthreads();
            for (int off = 512; off > 0; off >>= 1) {
                if (tid < off) {
                    float so = rs_[tid + off]; int io = ri_[tid + off];
                    if (so > rs_[tid] || (so == rs_[tid] && io < ri_[tid])) {
                        rs_[tid] = so; ri_[tid] = io;
                    }
                }
                __syncthreads();
            }
            float topS = rs_[0]; int top = ri_[0];
            __syncthreads();
            if (topS < 0.0f) break;

            if (tid == 0) sm->keep[kept] = top;     // ORIGINAL index
            kept++;

            float4 bt = g_boxes[top];
            float at = box_area(bt);
            for (int i = tid; i < N_PRIORS; i += 1024) {
                float4 bx = g_boxes[i];
                if (iou_gt(bt, at, bx, box_area(bx)))
                    atomicOr(&g_supp[i >> 5], 1u << (i & 31));
            }
            __syncthreads();
        }
        if (tid == 0) { sm->s_kept = kept; sm->s_keepmode = 1; }
        __syncthreads();
    }

    // ---- finalize ----
    {
        int kept = sm->s_kept;
        int mode = sm->s_keepmode;
        float thr = thrp[0];

        if (tid < MAXK) {
            int i = tid;
            float* ob = out;                 // [750,4]
            float* os = out + MAXK * 4;      // [750]
            float* ol = out + MAXK * 5;      // [750,10]

            float4 b = make_float4(0.f, 0.f, 0.f, 0.f);
            float s = 0.f;
            float lm[10];
            #pragma unroll
            for (int j = 0; j < 10; j++) lm[j] = 0.f;

            if (i < kept) {
                int orig;
                if (mode == 0) orig = sm->sorder[sm->keep[i]];
                else           orig = sm->keep[i];
                float sc = scores[orig];
                if (sc > thr) {
                    b = g_boxes[orig];
                    s = sc;
                    float px, py, ps;
                    get_prior(orig, px, py, ps);
                    #pragma unroll
                    for (int j = 0; j < 5; j++) {
                        float ox = landms[10 * orig + 2 * j + 0];
                        float oy = landms[10 * orig + 2 * j + 1];
                        lm[2 * j + 0] = __fmul_rn(__fadd_rn(px, __fmul_rn(__fmul_rn(ox, 0.1f), ps)), 2560.0f);
                        lm[2 * j + 1] = __fmul_rn(__fadd_rn(py, __fmul_rn(__fmul_rn(oy, 0.1f), ps)), 2560.0f);
                    }
                }
            }
            ob[4 * i + 0] = b.x;
            ob[4 * i + 1] = b.y;
            ob[4 * i + 2] = b.z;
            ob[4 * i + 3] = b.w;
            os[i] = s;
            #pragma unroll
            for (int j = 0; j < 10; j++) ol[10 * i + j] = lm[j];
        }
    }

    __syncthreads();
    if (tid == 0) g_cnt = 0;     // tail reset for next graph replay
}

// ---------------- launch ----------------
extern "C" void kernel_launch(void* const* d_in, const int* in_sizes, int n_in,
                              void* d_out, int out_size) {
    const float* bboxes = (const float*)d_in[0];   // (1, N, 4)
    const float* scores = (const float*)d_in[1];   // (1, N)
    const float* landms = (const float*)d_in[2];   // (1, N, 10)
    const float* thr    = (const float*)d_in[3];   // (1,)
    float* out = (float*)d_out;
    cudaStream_t stream = 0;

    static const int SMEM_BYTES = (int)sizeof(ScanSmem);
    cudaFuncSetAttribute(scanfin_kernel,
                         cudaFuncAttributeMaxDynamicSharedMemorySize, SMEM_BYTES);

    decode_kernel<<<N_PRIORS / 256, 256, 0, stream>>>(bboxes, scores);
    rank_kernel<<<CAP / 128, 128, 0, stream>>>();
    mask_kernel<<<(M1 * W1) / 256, 256, 0, stream>>>();
    scanfin_kernel<<<1, 1024, SMEM_BYTES, stream>>>(scores, landms, thr, out);
}

// round 9
// speedup vs baseline: 5.8151x; 1.1429x over previous
#include <cuda_runtime.h>
#include <cstdint>
#include <math.h>

#define N_PRIORS 268800
#define MAXK 750
#define CAP 2048            // candidate capacity
#define M1 1024             // bitmask NMS width
#define W1 16               // u64 words per mask row (M1/64)
#define CTHR 0.9966f        // E[ncand] ~ 914
#define NSUPW ((N_PRIORS + 31) / 32)
#define FULLM 0xffffffffu

// ---------------- static device scratch ----------------
__device__ float4 g_boxes[N_PRIORS];
__device__ unsigned long long g_ckeys[CAP];
__device__ int    g_cnt;                         // zero-init; reset at tail
__device__ int    g_ncand;
__device__ int    g_overflow;
__device__ int    g_sorder[CAP];                 // sorted original indices
__device__ float4 g_sbox[CAP];
__device__ float  g_sarea[CAP];
__device__ unsigned long long g_mask[M1 * W1];   // row i: bits j (j>i) i suppresses
__device__ unsigned int g_supp[NSUPW];           // fallback bitmap

// ---------------- priors, pure f32 (bit-identical to numpy f64->f32 path) -------
__device__ __forceinline__ void get_prior(int i, float& px, float& py, float& ps) {
    int r, f; float D, ps0, ps1;
    if (i < 204800)      { r = i;          f = 320; D = 640.0f;
                           ps0 = (float)(16.0  / 2560.0); ps1 = (float)(32.0  / 2560.0); }
    else if (i < 256000) { r = i - 204800; f = 160; D = 320.0f;
                           ps0 = (float)(64.0  / 2560.0); ps1 = (float)(128.0 / 2560.0); }
    else                 { r = i - 256000; f = 80;  D = 160.0f;
                           ps0 = (float)(256.0 / 2560.0); ps1 = (float)(512.0 / 2560.0); }
    int c = r >> 1;
    int x = c % f;
    int y = c / f;
    px = (float)(2 * x + 1) / D;
    py = (float)(2 * y + 1) / D;
    ps = (r & 1) ? ps1 : ps0;
}

__device__ __forceinline__ float box_area(const float4 b) {
    return __fmul_rn(__fadd_rn(__fsub_rn(b.z, b.x), 1.0f),
                     __fadd_rn(__fsub_rn(b.w, b.y), 1.0f));
}

// IoU > 0.4, op order mirrors reference. (bi,ai)=kept, (bj,aj)=candidate.
__device__ __forceinline__ bool iou_gt(const float4 bi, const float ai,
                                       const float4 bj, const float aj) {
    float xx1 = fmaxf(bi.x, bj.x);
    float yy1 = fmaxf(bi.y, bj.y);
    float xx2 = fminf(bi.z, bj.z);
    float yy2 = fminf(bi.w, bj.w);
    float iw = fmaxf(0.0f, __fadd_rn(__fsub_rn(xx2, xx1), 1.0f));
    float ih = fmaxf(0.0f, __fadd_rn(__fsub_rn(yy2, yy1), 1.0f));
    float inter = __fmul_rn(iw, ih);
    float uni = __fsub_rn(__fadd_rn(ai, aj), inter);
    return (inter / uni) > 0.4f;       // IEEE divide, like reference
}

// ---------------- decode all boxes + candidate selection ----------------
__global__ void decode_kernel(const float* __restrict__ loc,
                              const float* __restrict__ scores) {
    int i = blockIdx.x * blockDim.x + threadIdx.x;
    if (i >= N_PRIORS) return;

    float px, py, ps;
    get_prior(i, px, py, ps);

    float4 l = reinterpret_cast<const float4*>(loc)[i];

    float cx = __fadd_rn(px, __fmul_rn(__fmul_rn(l.x, 0.1f), ps));
    float cy = __fadd_rn(py, __fmul_rn(__fmul_rn(l.y, 0.1f), ps));
    float w = __fmul_rn(ps, expf(__fmul_rn(l.z, 0.2f)));
    float h = __fmul_rn(ps, expf(__fmul_rn(l.w, 0.2f)));

    float x1 = __fmul_rn(__fsub_rn(cx, __fmul_rn(w, 0.5f)), 2560.0f);
    float y1 = __fmul_rn(__fsub_rn(cy, __fmul_rn(h, 0.5f)), 2560.0f);
    float x2 = __fmul_rn(__fadd_rn(cx, __fmul_rn(w, 0.5f)), 2560.0f);
    float y2 = __fmul_rn(__fadd_rn(cy, __fmul_rn(h, 0.5f)), 2560.0f);

    g_boxes[i] = make_float4(x1, y1, x2, y2);

    float sc = scores[i];
    if (sc > CTHR) {
        int p = atomicAdd(&g_cnt, 1);
        if (p < CAP) {
            // descending score bits; ties -> ascending index (stable argsort)
            g_ckeys[p] = ((unsigned long long)__float_as_uint(sc) << 32)
                       | (unsigned long long)(0xFFFFFFFFu - (unsigned)i);
        }
    }
}

// ---------------- grid-wide O(n^2) rank sort (16 blocks x 128) ----------------
__global__ void rank_kernel() {
    __shared__ unsigned long long sk[CAP];       // 16 KB
    int tid = threadIdx.x;
    int cnt = g_cnt;
    int n = cnt < CAP ? cnt : CAP;

    for (int t = tid; t < n; t += 128) sk[t] = g_ckeys[t];
    __syncthreads();

    int t = blockIdx.x * 128 + tid;
    if (t < n) {
        unsigned long long k = sk[t];
        int rank = 0;
        #pragma unroll 8
        for (int j = 0; j < n; j++) rank += (sk[j] > k) ? 1 : 0;
        int idx = (int)(0xFFFFFFFFu - (unsigned)(k & 0xFFFFFFFFull));
        g_sorder[rank] = idx;
        float4 b = g_boxes[idx];
        g_sbox[rank] = b;
        g_sarea[rank] = box_area(b);
    }
    if (blockIdx.x == 0 && tid == 0) {
        g_ncand = n;
        g_overflow = (cnt > CAP) ? 1 : 0;
    }
}

// ---------------- grid-wide triangular suppression mask (64 blocks x 256) ------
__global__ void mask_kernel() {
    int t = blockIdx.x * blockDim.x + threadIdx.x;   // 16384 threads
    int i = t & (M1 - 1);          // consecutive lanes -> consecutive i
    int w = t >> 10;               // whole warp shares w -> g_sbox[j] broadcasts
    int jbase = w * 64;
    int n = g_ncand;
    int n1 = n < M1 ? n : M1;

    unsigned long long bits = 0ULL;
    if (i < n1 && jbase + 63 > i) {
        float4 bi = g_sbox[i];
        float ai = g_sarea[i];
        int jj0 = (i + 1 > jbase) ? (i + 1 - jbase) : 0;
        int jjend = (jbase + 64 <= n1) ? 64 : (n1 - jbase);
        #pragma unroll 4
        for (int jj = jj0; jj < jjend; jj++) {
            int j = jbase + jj;
            if (iou_gt(bi, ai, g_sbox[j], g_sarea[j])) bits |= (1ULL << jj);
        }
    }
    g_mask[i * W1 + w] = bits;
}

// ---------------- scan (1 warp, stripe-batched) + fallback + finalize ----------
struct ScanSmem {
    unsigned long long mask[M1 * W1];   // 128 KB
    int sorder[CAP];                    // 8 KB
    int keep[MAXK];
    int s_kept, s_done, s_keepmode;
};

__global__ void __launch_bounds__(1024, 1)
scanfin_kernel(const float* __restrict__ scores,
               const float* __restrict__ landms,
               const float* __restrict__ thrp,
               float* __restrict__ out) {
    extern __shared__ char smraw[];
    ScanSmem* sm = (ScanSmem*)smraw;
    int tid = threadIdx.x;
    int lane = tid & 31;

    int cnt = g_cnt;
    int n = cnt < CAP ? cnt : CAP;
    int n1 = n < M1 ? n : M1;

    if (tid == 0) { sm->s_kept = 0; sm->s_done = 0; sm->s_keepmode = 0; }

    // cooperative bulk copy: mask + sorder into smem (coalesced)
    {
        const uint4* src = (const uint4*)g_mask;
        uint4* dst = (uint4*)sm->mask;
        #pragma unroll
        for (int q = 0; q < (M1 * W1 * 8) / (16 * 1024); q++)
            dst[q * 1024 + tid] = src[q * 1024 + tid];
        for (int t = tid; t < n; t += 1024) sm->sorder[t] = g_sorder[t];
    }
    __syncthreads();

    // ---- single-warp greedy bit-scan, stripe-batched fast path ----
    if (tid < 32) {
        // word k of the running suppression OR is split across lanes k (rows u<32
        // of each stripe) and k+16 (rows u>=32). Combined on demand via 2 shfls.
        unsigned long long rem = 0ULL;
        const int myw = lane & 15;
        int kept = 0;
        bool done = false;

        for (int s = 0; s < W1 && !done; s++) {
            int p0 = s * 64;
            if (p0 >= n1) break;
            unsigned long long cur = __shfl_sync(FULLM, rem, s)
                                   | __shfl_sync(FULLM, rem, s + 16);
            int nrem = n1 - p0;
            unsigned long long valid = (nrem >= 64) ? ~0ULL : ((1ULL << nrem) - 1ULL);

            unsigned long long swA = sm->mask[(p0 + lane) * W1 + s];        // u = lane
            unsigned long long swB = sm->mask[(p0 + 32 + lane) * W1 + s];   // u = lane+32

            unsigned long long free64 = ~cur & valid;
            int nfree = __popcll(free64);

            // exact fast-path test: no free candidate suppresses a later free one
            bool vio = ((((free64 >> lane) & 1ULL) && (swA & free64)) ||
                        (((free64 >> (lane + 32)) & 1ULL) && (swB & free64)));
            unsigned vb = __ballot_sync(FULLM, vio);

            if (vb == 0u && kept + nfree <= MAXK) {
                // FAST: take all free candidates of this stripe
                unsigned lowm = (unsigned)free64;
                unsigned highm = (unsigned)(free64 >> 32);
                if ((lowm >> lane) & 1u) {
                    int pos = kept + __popc(lowm & ((1u << lane) - 1u));
                    sm->keep[pos] = p0 + lane;
                }
                if ((highm >> lane) & 1u) {
                    int pos = kept + __popc(lowm) + __popc(highm & ((1u << lane) - 1u));
                    sm->keep[pos] = p0 + 32 + lane;
                }
                unsigned mbits = (lane < 16) ? lowm : highm;
                int ubase = (lane < 16) ? 0 : 32;
                #pragma unroll
                for (int u = 0; u < 32; u++) {
                    if ((mbits >> u) & 1u)
                        rem |= sm->mask[(p0 + ubase + u) * W1 + myw];
                }
                kept += nfree;
                if (kept >= MAXK) done = true;
            } else {
                // SLOW: serial in-stripe walk (rare)
                #pragma unroll
                for (int u = 0; u < 64; u++) {
                    unsigned long long rs =
                        __shfl_sync(FULLM, (u < 32) ? swA : swB, u & 31);
                    bool take = ((valid >> u) & 1ULL) && !((cur >> u) & 1ULL)
                                && (kept < MAXK);
                    if (take) {
                        cur |= rs;                                  // warp-uniform
                        if ((lane < 16) == (u < 32))
                            rem |= sm->mask[(p0 + u) * W1 + myw];
                        if (lane == 0) sm->keep[kept] = p0 + u;
                        kept++;
                    }
                }
                if (kept >= MAXK) done = true;
            }
        }

        // continuation over candidates beyond M1 (structurally ~never runs)
        if (kept < MAXK && n > n1) {
            __syncwarp();
            for (int p = n1; p < n && kept < MAXK; p++) {
                float4 bj = g_sbox[p];
                float aj = g_sarea[p];
                bool hit = false;
                for (int t = lane; t < kept; t += 32) {
                    int kp = sm->keep[t];
                    if (iou_gt(g_sbox[kp], g_sarea[kp], bj, aj)) hit = true;
                }
                if (__ballot_sync(FULLM, hit) == 0u) {
                    if (lane == 0) sm->keep[kept] = p;
                    kept++;
                    __syncwarp();
                }
            }
        }

        if (lane == 0) {
            sm->s_kept = kept;
            sm->s_done = (kept >= MAXK && cnt <= CAP) ? 1 : 0;
        }
    }
    __syncthreads();

    // ---- guaranteed-correct fallback (expected no-op; uniform branch) ----
    if (!sm->s_done) {
        __shared__ float rs_[1024];
        __shared__ int   ri_[1024];
        for (int w = tid; w < NSUPW; w += 1024) g_supp[w] = 0u;
        __syncthreads();

        int kept = 0;
        for (int it = 0; it < MAXK; it++) {
            float bs = -1.0f; int bi = 0x7FFFFFFF;
            for (int i = tid; i < N_PRIORS; i += 1024) {
                if (!((g_supp[i >> 5] >> (i & 31)) & 1u)) {
                    float s = scores[i];
                    if (s > bs || (s == bs && i < bi)) { bs = s; bi = i; }
                }
            }
            rs_[tid] = bs; ri_[tid] = bi;
            __syncthreads();
            for (int off = 512; off > 0; off >>= 1) {
                if (tid < off) {
                    float so = rs_[tid + off]; int io = ri_[tid + off];
                    if (so > rs_[tid] || (so == rs_[tid] && io < ri_[tid])) {
                        rs_[tid] = so; ri_[tid] = io;
                    }
                }
                __syncthreads();
            }
            float topS = rs_[0]; int top = ri_[0];
            __syncthreads();
            if (topS < 0.0f) break;

            if (tid == 0) sm->keep[kept] = top;     // ORIGINAL index
            kept++;

            float4 bt = g_boxes[top];
            float at = box_area(bt);
            for (int i = tid; i < N_PRIORS; i += 1024) {
                float4 bx = g_boxes[i];
                if (iou_gt(bt, at, bx, box_area(bx)))
                    atomicOr(&g_supp[i >> 5], 1u << (i & 31));
            }
            __syncthreads();
        }
        if (tid == 0) { sm->s_kept = kept; sm->s_keepmode = 1; }
        __syncthreads();
    }

    // ---- finalize ----
    {
        int kept = sm->s_kept;
        int mode = sm->s_keepmode;
        float thr = thrp[0];

        if (tid < MAXK) {
            int i = tid;
            float* ob = out;                 // [750,4]
            float* os = out + MAXK * 4;      // [750]
            float* ol = out + MAXK * 5;      // [750,10]

            float4 b = make_float4(0.f, 0.f, 0.f, 0.f);
            float s = 0.f;
            float lm[10];
            #pragma unroll
            for (int j = 0; j < 10; j++) lm[j] = 0.f;

            if (i < kept) {
                int orig;
                if (mode == 0) orig = sm->sorder[sm->keep[i]];
                else           orig = sm->keep[i];
                float sc = scores[orig];
                if (sc > thr) {
                    b = g_boxes[orig];
                    s = sc;
                    float px, py, ps;
                    get_prior(orig, px, py, ps);
                    #pragma unroll
                    for (int j = 0; j < 5; j++) {
                        float ox = landms[10 * orig + 2 * j + 0];
                        float oy = landms[10 * orig + 2 * j + 1];
                        lm[2 * j + 0] = __fmul_rn(__fadd_rn(px, __fmul_rn(__fmul_rn(ox, 0.1f), ps)), 2560.0f);
                        lm[2 * j + 1] = __fmul_rn(__fadd_rn(py, __fmul_rn(__fmul_rn(oy, 0.1f), ps)), 2560.0f);
                    }
                }
            }
            ob[4 * i + 0] = b.x;
            ob[4 * i + 1] = b.y;
            ob[4 * i + 2] = b.z;
            ob[4 * i + 3] = b.w;
            os[i] = s;
            #pragma unroll
            for (int j = 0; j < 10; j++) ol[10 * i + j] = lm[j];
        }
    }

    __syncthreads();
    if (tid == 0) g_cnt = 0;     // tail reset for next graph replay
}

// ---------------- launch ----------------
extern "C" void kernel_launch(void* const* d_in, const int* in_sizes, int n_in,
                              void* d_out, int out_size) {
    const float* bboxes = (const float*)d_in[0];   // (1, N, 4)
    const float* scores = (const float*)d_in[1];   // (1, N)
    const float* landms = (const float*)d_in[2];   // (1, N, 10)
    const float* thr    = (const float*)d_in[3];   // (1,)
    float* out = (float*)d_out;
    cudaStream_t stream = 0;

    static const int SMEM_BYTES = (int)sizeof(ScanSmem);
    cudaFuncSetAttribute(scanfin_kernel,
                         cudaFuncAttributeMaxDynamicSharedMemorySize, SMEM_BYTES);

    decode_kernel<<<N_PRIORS / 256, 256, 0, stream>>>(bboxes, scores);
    rank_kernel<<<CAP / 128, 128, 0, stream>>>();
    mask_kernel<<<(M1 * W1) / 256, 256, 0, stream>>>();
    scanfin_kernel<<<1, 1024, SMEM_BYTES, stream>>>(scores, landms, thr, out);
}

// round 10
// speedup vs baseline: 7.3583x; 1.2654x over previous
#include <cuda_runtime.h>
#include <cstdint>
#include <math.h>

#define N_PRIORS 268800
#define MAXK 750
#define CAP 2048            // candidate capacity (score > CTHR)
#define CTHR 0.9966f        // E[ncand] ~ 914
#define SUPK 32             // max recorded suppressors per candidate
#define AMB_MAX 64          // max ambiguous candidates on fast path
#define NSUPW ((N_PRIORS + 31) / 32)
#define FULLM 0xffffffffu

// ---------------- static device scratch ----------------
__device__ float4 g_boxes[N_PRIORS];
__device__ unsigned long long g_ckeys[CAP];
__device__ int    g_cnt;                       // zero-init; reset at tail
__device__ int    g_ncand;
__device__ int    g_sorder[CAP];               // sorted original indices
__device__ float4 g_sbox[CAP];
__device__ float  g_sarea[CAP];
__device__ int    g_supcnt[CAP];               // zero-init; reset at tail
__device__ int    g_suplist[CAP * SUPK];
__device__ unsigned int g_supp[NSUPW];         // fallback bitmap

// ---------------- priors, pure f32 (bit-identical to numpy f64->f32 path) -------
__device__ __forceinline__ void get_prior(int i, float& px, float& py, float& ps) {
    int r, f; float D, ps0, ps1;
    if (i < 204800)      { r = i;          f = 320; D = 640.0f;
                           ps0 = (float)(16.0  / 2560.0); ps1 = (float)(32.0  / 2560.0); }
    else if (i < 256000) { r = i - 204800; f = 160; D = 320.0f;
                           ps0 = (float)(64.0  / 2560.0); ps1 = (float)(128.0 / 2560.0); }
    else                 { r = i - 256000; f = 80;  D = 160.0f;
                           ps0 = (float)(256.0 / 2560.0); ps1 = (float)(512.0 / 2560.0); }
    int c = r >> 1;
    int x = c % f;
    int y = c / f;
    px = (float)(2 * x + 1) / D;
    py = (float)(2 * y + 1) / D;
    ps = (r & 1) ? ps1 : ps0;
}

__device__ __forceinline__ float box_area(const float4 b) {
    return __fmul_rn(__fadd_rn(__fsub_rn(b.z, b.x), 1.0f),
                     __fadd_rn(__fsub_rn(b.w, b.y), 1.0f));
}

// IoU > 0.4, op order mirrors reference. (bi,ai)=kept/earlier, (bj,aj)=candidate.
__device__ __forceinline__ bool iou_gt(const float4 bi, const float ai,
                                       const float4 bj, const float aj) {
    float xx1 = fmaxf(bi.x, bj.x);
    float yy1 = fmaxf(bi.y, bj.y);
    float xx2 = fminf(bi.z, bj.z);
    float yy2 = fminf(bi.w, bj.w);
    float iw = fmaxf(0.0f, __fadd_rn(__fsub_rn(xx2, xx1), 1.0f));
    float ih = fmaxf(0.0f, __fadd_rn(__fsub_rn(yy2, yy1), 1.0f));
    float inter = __fmul_rn(iw, ih);
    float uni = __fsub_rn(__fadd_rn(ai, aj), inter);
    return (inter / uni) > 0.4f;       // IEEE divide, like reference
}

// ---------------- decode all boxes + candidate selection ----------------
__global__ void decode_kernel(const float* __restrict__ loc,
                              const float* __restrict__ scores) {
    int i = blockIdx.x * blockDim.x + threadIdx.x;
    if (i >= N_PRIORS) return;

    float px, py, ps;
    get_prior(i, px, py, ps);

    float4 l = reinterpret_cast<const float4*>(loc)[i];

    float cx = __fadd_rn(px, __fmul_rn(__fmul_rn(l.x, 0.1f), ps));
    float cy = __fadd_rn(py, __fmul_rn(__fmul_rn(l.y, 0.1f), ps));
    float w = __fmul_rn(ps, expf(__fmul_rn(l.z, 0.2f)));
    float h = __fmul_rn(ps, expf(__fmul_rn(l.w, 0.2f)));

    float x1 = __fmul_rn(__fsub_rn(cx, __fmul_rn(w, 0.5f)), 2560.0f);
    float y1 = __fmul_rn(__fsub_rn(cy, __fmul_rn(h, 0.5f)), 2560.0f);
    float x2 = __fmul_rn(__fadd_rn(cx, __fmul_rn(w, 0.5f)), 2560.0f);
    float y2 = __fmul_rn(__fadd_rn(cy, __fmul_rn(h, 0.5f)), 2560.0f);

    g_boxes[i] = make_float4(x1, y1, x2, y2);

    float sc = scores[i];
    if (sc > CTHR) {
        int p = atomicAdd(&g_cnt, 1);
        if (p < CAP) {
            // descending score bits; ties -> ascending index (stable argsort)
            g_ckeys[p] = ((unsigned long long)__float_as_uint(sc) << 32)
                       | (unsigned long long)(0xFFFFFFFFu - (unsigned)i);
        }
    }
}

// ---------------- grid-wide O(n^2) rank sort (16 blocks x 128) ----------------
__global__ void rank_kernel() {
    __shared__ unsigned long long sk[CAP];       // 16 KB
    int tid = threadIdx.x;
    int cnt = g_cnt;
    int n = cnt < CAP ? cnt : CAP;

    for (int t = tid; t < n; t += 128) sk[t] = g_ckeys[t];
    __syncthreads();

    int t = blockIdx.x * 128 + tid;
    if (t < n) {
        unsigned long long k = sk[t];
        int rank = 0;
        #pragma unroll 8
        for (int j = 0; j < n; j++) rank += (sk[j] > k) ? 1 : 0;
        int idx = (int)(0xFFFFFFFFu - (unsigned)(k & 0xFFFFFFFFull));
        g_sorder[rank] = idx;
        float4 b = g_boxes[idx];
        g_sbox[rank] = b;
        g_sarea[rank] = box_area(b);
    }
    if (blockIdx.x == 0 && tid == 0) g_ncand = n;
}

// ---------------- sparse suppressor lists: all pairs i<j with IoU>0.4 ----------
__global__ void suppress_kernel() {
    int t = blockIdx.x * blockDim.x + threadIdx.x;   // CAP * (CAP/64) threads
    int i = t & (CAP - 1);         // consecutive lanes -> consecutive i (coalesced)
    int w = t >> 11;               // 0..31; whole warp shares w -> j loads broadcast
    int jbase = w * 64;
    int n = g_ncand;

    if (i >= n || jbase + 63 <= i) return;
    float4 bi = g_sbox[i];
    float ai = g_sarea[i];
    int j0 = (i + 1 > jbase) ? i + 1 : jbase;
    int j1 = (jbase + 64 < n) ? jbase + 64 : n;
    for (int j = j0; j < j1; j++) {
        if (iou_gt(bi, ai, g_sbox[j], g_sarea[j])) {
            int slot = atomicAdd(&g_supcnt[j], 1);
            if (slot < SUPK) g_suplist[j * SUPK + slot] = i;
        }
    }
}

// ---------------- resolve kept set + finalize (+ reference fallback) ------------
__global__ void __launch_bounds__(1024, 1)
resolve_kernel(const float* __restrict__ scores,
               const float* __restrict__ landms,
               const float* __restrict__ thrp,
               float* __restrict__ out) {
    __shared__ unsigned char s_kept[CAP];
    __shared__ int  s_cnt[CAP];
    __shared__ unsigned int s_kb[64], s_ab[64];
    __shared__ int  s_wbase[64], s_awbase[64];
    __shared__ int  s_alist[AMB_MAX];
    __shared__ int  s_asup[AMB_MAX * 32];
    __shared__ int  s_keep_orig[MAXK];       // fallback keep list (original indices)
    __shared__ int  s_namb, s_ktot, s_fkept;
    __shared__ float rs_[1024];
    __shared__ int   ri_[1024];

    int tid = threadIdx.x;
    int lane = tid & 31;
    int wi = tid >> 5;                       // 0..31
    unsigned lt = (1u << lane) - 1u;

    int cnt_all = g_cnt;
    int n = cnt_all < CAP ? cnt_all : CAP;
    int j1 = tid, j2 = tid + 1024;

    // ---- load suppressor counts, init kept / ambig flags ----
    int c1 = (j1 < n) ? g_supcnt[j1] : 0;
    int c2 = (j2 < n) ? g_supcnt[j2] : 0;
    s_cnt[j1] = c1;
    s_cnt[j2] = c2;
    bool a1 = (j1 < n) && (c1 > 0);
    bool a2 = (j2 < n) && (c2 > 0);
    s_kept[j1] = ((j1 < n) && c1 == 0) ? 1 : 0;
    s_kept[j2] = ((j2 < n) && c2 == 0) ? 1 : 0;
    int ovf = __syncthreads_or((c1 > SUPK) || (c2 > SUPK));

    // ---- ambiguous-candidate ordered list via ballot prefix-scan ----
    {
        unsigned b1 = __ballot_sync(FULLM, a1);
        unsigned b2 = __ballot_sync(FULLM, a2);
        if (lane == 0) { s_ab[wi] = b1; s_ab[32 + wi] = b2; }
    }
    __syncthreads();
    if (tid < 32) {
        int cA = __popc(s_ab[tid]);
        int cB = __popc(s_ab[tid + 32]);
        int sA = cA, sB = cB;
        #pragma unroll
        for (int o = 1; o < 32; o <<= 1) { int v = __shfl_up_sync(FULLM, sA, o); if (lane >= o) sA += v; }
        int totA = __shfl_sync(FULLM, sA, 31);
        #pragma unroll
        for (int o = 1; o < 32; o <<= 1) { int v = __shfl_up_sync(FULLM, sB, o); if (lane >= o) sB += v; }
        int totB = __shfl_sync(FULLM, sB, 31);
        s_awbase[tid] = sA - cA;
        s_awbase[tid + 32] = totA + sB - cB;
        if (tid == 0) s_namb = totA + totB;
    }
    __syncthreads();
    int namb = s_namb;

    if (a1) { int r = s_awbase[wi] + __popc(s_ab[wi] & lt); if (r < AMB_MAX) s_alist[r] = j1; }
    if (a2) { int r = s_awbase[32 + wi] + __popc(s_ab[32 + wi] & lt); if (r < AMB_MAX) s_alist[r] = j2; }
    __syncthreads();

    // ---- bulk preload suppressor entries for ambiguous js ----
    if (namb <= AMB_MAX) {
        for (int idx = tid; idx < namb * 32; idx += 1024) {
            int a = idx >> 5, l = idx & 31;
            int j = s_alist[a];
            int c = s_cnt[j]; if (c > SUPK) c = SUPK;
            if (l < c) s_asup[idx] = g_suplist[j * SUPK + l];
        }
    }
    __syncthreads();

    // ---- tiny serial resolution (ambiguous js in ascending order) ----
    if (tid == 0 && namb <= AMB_MAX) {
        for (int a = 0; a < namb; a++) {
            int j = s_alist[a];
            int c = s_cnt[j]; if (c > SUPK) c = SUPK;
            int k = 1;
            for (int l = 0; l < c; l++)
                if (s_kept[s_asup[a * 32 + l]]) { k = 0; break; }
            s_kept[j] = (unsigned char)k;
        }
    }
    __syncthreads();

    // ---- kept ranks via ballot prefix-scan ----
    bool k1 = s_kept[j1] != 0;
    bool k2 = s_kept[j2] != 0;
    {
        unsigned b1 = __ballot_sync(FULLM, k1);
        unsigned b2 = __ballot_sync(FULLM, k2);
        if (lane == 0) { s_kb[wi] = b1; s_kb[32 + wi] = b2; }
    }
    __syncthreads();
    if (tid < 32) {
        int cA = __popc(s_kb[tid]);
        int cB = __popc(s_kb[tid + 32]);
        int sA = cA, sB = cB;
        #pragma unroll
        for (int o = 1; o < 32; o <<= 1) { int v = __shfl_up_sync(FULLM, sA, o); if (lane >= o) sA += v; }
        int totA = __shfl_sync(FULLM, sA, 31);
        #pragma unroll
        for (int o = 1; o < 32; o <<= 1) { int v = __shfl_up_sync(FULLM, sB, o); if (lane >= o) sB += v; }
        int totB = __shfl_sync(FULLM, sB, 31);
        s_wbase[tid] = sA - cA;
        s_wbase[tid + 32] = totA + sB - cB;
        if (tid == 0) s_ktot = totA + totB;
    }
    __syncthreads();
    int ktot = s_ktot;

    bool fb = ovf || (cnt_all > CAP) || (namb > AMB_MAX) || (ktot < MAXK);

    float thr = thrp[0];
    float* ob = out;                 // [750,4]
    float* os = out + MAXK * 4;      // [750]
    float* ol = out + MAXK * 5;      // [750,10]

    if (!fb) {
        // ---- FAST finalize ----
        if (tid < MAXK) {
            int r = tid;
            ob[4 * r + 0] = 0.f; ob[4 * r + 1] = 0.f;
            ob[4 * r + 2] = 0.f; ob[4 * r + 3] = 0.f;
            os[r] = 0.f;
            #pragma unroll
            for (int q = 0; q < 10; q++) ol[10 * r + q] = 0.f;
        }
        __syncthreads();
        #pragma unroll
        for (int h = 0; h < 2; h++) {
            int j = tid + h * 1024;
            bool kp = (h == 0) ? k1 : k2;
            if (kp) {
                int w = j >> 5;
                int r = s_wbase[w] + __popc(s_kb[w] & lt);
                if (r < MAXK) {
                    int orig = g_sorder[j];
                    float sc = scores[orig];
                    if (sc > thr) {
                        float4 b = g_sbox[j];
                        ob[4 * r + 0] = b.x; ob[4 * r + 1] = b.y;
                        ob[4 * r + 2] = b.z; ob[4 * r + 3] = b.w;
                        os[r] = sc;
                        float px, py, ps;
                        get_prior(orig, px, py, ps);
                        #pragma unroll
                        for (int q = 0; q < 5; q++) {
                            float ox = landms[10 * orig + 2 * q + 0];
                            float oy = landms[10 * orig + 2 * q + 1];
                            ol[10 * r + 2 * q + 0] = __fmul_rn(__fadd_rn(px, __fmul_rn(__fmul_rn(ox, 0.1f), ps)), 2560.0f);
                            ol[10 * r + 2 * q + 1] = __fmul_rn(__fadd_rn(py, __fmul_rn(__fmul_rn(oy, 0.1f), ps)), 2560.0f);
                        }
                    }
                }
            }
        }
    } else {
        // ---- guaranteed-correct full reference fallback ----
        for (int w = tid; w < NSUPW; w += 1024) g_supp[w] = 0u;
        __syncthreads();

        int kept = 0;
        for (int it = 0; it < MAXK; it++) {
            float bs = -1.0f; int bi = 0x7FFFFFFF;
            for (int i = tid; i < N_PRIORS; i += 1024) {
                if (!((g_supp[i >> 5] >> (i & 31)) & 1u)) {
                    float s = scores[i];
                    if (s > bs || (s == bs && i < bi)) { bs = s; bi = i; }
                }
            }
            rs_[tid] = bs; ri_[tid] = bi;
            __syncthreads();
            for (int off = 512; off > 0; off >>= 1) {
                if (tid < off) {
                    float so = rs_[tid + off]; int io = ri_[tid + off];
                    if (so > rs_[tid] || (so == rs_[tid] && io < ri_[tid])) {
                        rs_[tid] = so; ri_[tid] = io;
                    }
                }
                __syncthreads();
            }
            float topS = rs_[0]; int top = ri_[0];
            __syncthreads();
            if (topS < 0.0f) break;

            if (tid == 0) s_keep_orig[kept] = top;
            kept++;

            float4 bt = g_boxes[top];
            float at = box_area(bt);
            for (int i = tid; i < N_PRIORS; i += 1024) {
                float4 bx = g_boxes[i];
                if (iou_gt(bt, at, bx, box_area(bx)))
                    atomicOr(&g_supp[i >> 5], 1u << (i & 31));
            }
            __syncthreads();
        }
        if (tid == 0) s_fkept = kept;
        __syncthreads();
        int fkept = s_fkept;

        if (tid < MAXK) {
            int i = tid;
            float4 b = make_float4(0.f, 0.f, 0.f, 0.f);
            float s = 0.f;
            float lm[10];
            #pragma unroll
            for (int q = 0; q < 10; q++) lm[q] = 0.f;

            if (i < fkept) {
                int orig = s_keep_orig[i];
                float sc = scores[orig];
                if (sc > thr) {
                    b = g_boxes[orig];
                    s = sc;
                    float px, py, ps;
                    get_prior(orig, px, py, ps);
                    #pragma unroll
                    for (int q = 0; q < 5; q++) {
                        float ox = landms[10 * orig + 2 * q + 0];
                        float oy = landms[10 * orig + 2 * q + 1];
                        lm[2 * q + 0] = __fmul_rn(__fadd_rn(px, __fmul_rn(__fmul_rn(ox, 0.1f), ps)), 2560.0f);
                        lm[2 * q + 1] = __fmul_rn(__fadd_rn(py, __fmul_rn(__fmul_rn(oy, 0.1f), ps)), 2560.0f);
                    }
                }
            }
            ob[4 * i + 0] = b.x; ob[4 * i + 1] = b.y;
            ob[4 * i + 2] = b.z; ob[4 * i + 3] = b.w;
            os[i] = s;
            #pragma unroll
            for (int q = 0; q < 10; q++) ol[10 * i + q] = lm[q];
        }
    }

    // ---- tail reset for next graph replay ----
    __syncthreads();
    g_supcnt[j1] = 0;
    g_supcnt[j2] = 0;
    if (tid == 0) g_cnt = 0;
}

// ---------------- launch ----------------
extern "C" void kernel_launch(void* const* d_in, const int* in_sizes, int n_in,
                              void* d_out, int out_size) {
    const float* bboxes = (const float*)d_in[0];   // (1, N, 4)
    const float* scores = (const float*)d_in[1];   // (1, N)
    const float* landms = (const float*)d_in[2];   // (1, N, 10)
    const float* thr    = (const float*)d_in[3];   // (1,)
    float* out = (float*)d_out;
    cudaStream_t stream = 0;

    decode_kernel<<<N_PRIORS / 256, 256, 0, stream>>>(bboxes, scores);
    rank_kernel<<<CAP / 128, 128, 0, stream>>>();
    suppress_kernel<<<(CAP * (CAP / 64)) / 256, 256, 0, stream>>>();
    resolve_kernel<<<1, 1024, 0, stream>>>(scores, landms, thr, out);
}

// round 14
// speedup vs baseline: 9.7694x; 1.3277x over previous
#include <cuda_runtime.h>
#include <cstdint>
#include <math.h>

#define N_PRIORS 268800
#define MAXK 750
#define CAP 2048            // candidate slot capacity (score > CTHR)
#define CTHR 0.9966f        // E[ncand] ~ 914
#define SUPK 32             // max recorded suppressors per candidate
#define AMB_MAX 64          // max ambiguous candidates on fast path
#define NSUPW ((N_PRIORS + 31) / 32)
#define FULLM 0xffffffffu

// ---------------- static device scratch ----------------
__device__ float4 g_boxes[N_PRIORS];            // FALLBACK-ONLY scratch
__device__ unsigned long long g_ckeys[CAP];     // candidate keys (slot order)
__device__ float4 g_cbox[CAP];
__device__ float  g_carea[CAP];
__device__ int    g_cnt;                        // zero-init; reset at tail
__device__ int    g_rank[CAP];                  // slot -> rank
__device__ int    g_slotofrank[CAP];            // rank -> slot
__device__ int    g_supcnt[CAP];                // zero-init; reset at tail
__device__ int    g_suplist[CAP * SUPK];        // suppressor slots
__device__ unsigned int g_supp[NSUPW];          // fallback bitmap

// ---------------- priors, pure f32 (bit-identical to numpy f64->f32 path) -------
__device__ __forceinline__ void get_prior(int i, float& px, float& py, float& ps) {
    int r, f; float D, ps0, ps1;
    if (i < 204800)      { r = i;          f = 320; D = 640.0f;
                           ps0 = (float)(16.0  / 2560.0); ps1 = (float)(32.0  / 2560.0); }
    else if (i < 256000) { r = i - 204800; f = 160; D = 320.0f;
                           ps0 = (float)(64.0  / 2560.0); ps1 = (float)(128.0 / 2560.0); }
    else                 { r = i - 256000; f = 80;  D = 160.0f;
                           ps0 = (float)(256.0 / 2560.0); ps1 = (float)(512.0 / 2560.0); }
    int c = r >> 1;
    int x = c % f;
    int y = c / f;
    px = (float)(2 * x + 1) / D;
    py = (float)(2 * y + 1) / D;
    ps = (r & 1) ? ps1 : ps0;
}

__device__ __forceinline__ float4 decode_box(const float4 l, float px, float py, float ps) {
    float cx = __fadd_rn(px, __fmul_rn(__fmul_rn(l.x, 0.1f), ps));
    float cy = __fadd_rn(py, __fmul_rn(__fmul_rn(l.y, 0.1f), ps));
    float w = __fmul_rn(ps, expf(__fmul_rn(l.z, 0.2f)));
    float h = __fmul_rn(ps, expf(__fmul_rn(l.w, 0.2f)));
    float x1 = __fmul_rn(__fsub_rn(cx, __fmul_rn(w, 0.5f)), 2560.0f);
    float y1 = __fmul_rn(__fsub_rn(cy, __fmul_rn(h, 0.5f)), 2560.0f);
    float x2 = __fmul_rn(__fadd_rn(cx, __fmul_rn(w, 0.5f)), 2560.0f);
    float y2 = __fmul_rn(__fadd_rn(cy, __fmul_rn(h, 0.5f)), 2560.0f);
    return make_float4(x1, y1, x2, y2);
}

__device__ __forceinline__ float box_area(const float4 b) {
    return __fmul_rn(__fadd_rn(__fsub_rn(b.z, b.x), 1.0f),
                     __fadd_rn(__fsub_rn(b.w, b.y), 1.0f));
}

// IoU > 0.4 with +1 convention; FP-symmetric in operand order (IEEE add/mul
// commutative, min/max symmetric), so caller order doesn't matter.
__device__ __forceinline__ bool iou_gt(const float4 bi, const float ai,
                                       const float4 bj, const float aj) {
    float xx1 = fmaxf(bi.x, bj.x);
    float yy1 = fmaxf(bi.y, bj.y);
    float xx2 = fminf(bi.z, bj.z);
    float yy2 = fminf(bi.w, bj.w);
    float iw = fmaxf(0.0f, __fadd_rn(__fsub_rn(xx2, xx1), 1.0f));
    float ih = fmaxf(0.0f, __fadd_rn(__fsub_rn(yy2, yy1), 1.0f));
    float inter = __fmul_rn(iw, ih);
    float uni = __fsub_rn(__fadd_rn(ai, aj), inter);
    return (inter / uni) > 0.4f;       // IEEE divide, like reference
}

// ---------------- decode: candidates only ----------------
__global__ void decode_kernel(const float* __restrict__ loc,
                              const float* __restrict__ scores) {
    int i = blockIdx.x * blockDim.x + threadIdx.x;
    if (i >= N_PRIORS) return;

    float sc = scores[i];
    if (sc > CTHR) {
        int p = atomicAdd(&g_cnt, 1);
        if (p < CAP) {
            float px, py, ps;
            get_prior(i, px, py, ps);
            float4 l = reinterpret_cast<const float4*>(loc)[i];
            float4 b = decode_box(l, px, py, ps);
            // descending score bits; ties -> ascending index (stable argsort)
            g_ckeys[p] = ((unsigned long long)__float_as_uint(sc) << 32)
                       | (unsigned long long)(0xFFFFFFFFu - (unsigned)i);
            g_cbox[p] = b;
            g_carea[p] = box_area(b);
        }
    }
}

// ---------------- rank (blocks 0-7) || suppress (blocks 8-263) ----------------
__global__ void ranksup_kernel() {
    int cnt = g_cnt;
    int n = cnt < CAP ? cnt : CAP;
    int tid = threadIdx.x;

    if (blockIdx.x < 8) {
        // ---- O(n^2) rank sort over slots (unique keys -> exact stable ranks) ----
        __shared__ unsigned long long sk[CAP];       // 16 KB
        for (int t = tid; t < n; t += 256) sk[t] = g_ckeys[t];
        __syncthreads();
        int t = blockIdx.x * 256 + tid;
        if (t < n) {
            unsigned long long k = sk[t];
            int rank = 0;
            #pragma unroll 8
            for (int j = 0; j < n; j++) rank += (sk[j] > k) ? 1 : 0;
            g_rank[t] = rank;
            g_slotofrank[rank] = t;
        }
    } else {
        // ---- sparse suppression edges over unsorted slot pairs ----
        int t = (blockIdx.x - 8) * 256 + tid;        // [0, 65536)
        int i = t & (CAP - 1);         // consecutive lanes -> consecutive i
        int w = t >> 11;               // 0..31; warp-shared -> j loads broadcast
        int jbase = w * 64;
        if (i >= n || jbase + 63 <= i) return;
        float4 bi = g_cbox[i];
        float ai = g_carea[i];
        unsigned long long ki = g_ckeys[i];
        int j0 = (i + 1 > jbase) ? i + 1 : jbase;
        int j1 = (jbase + 64 < n) ? jbase + 64 : n;
        for (int j = j0; j < j1; j++) {
            if (iou_gt(bi, ai, g_cbox[j], g_carea[j])) {
                unsigned long long kj = g_ckeys[j];
                int supd = (ki > kj) ? j : i;        // smaller key is suppressed
                int supr = (ki > kj) ? i : j;
                int slot = atomicAdd(&g_supcnt[supd], 1);
                if (slot < SUPK) g_suplist[supd * SUPK + slot] = supr;
            }
        }
    }
}

// ---------------- resolve kept set + finalize (+ reference fallback) ------------
__global__ void __launch_bounds__(1024, 1)
resolve_kernel(const float* __restrict__ loc,
               const float* __restrict__ scores,
               const float* __restrict__ landms,
               const float* __restrict__ thrp,
               float* __restrict__ out) {
    __shared__ unsigned char s_kept[CAP];
    __shared__ int  s_cnt[CAP];
    __shared__ unsigned int s_kb[64], s_ab[64];
    __shared__ int  s_wbase[64], s_awbase[64];
    __shared__ int  s_alist[AMB_MAX], s_alist2[AMB_MAX], s_arank[AMB_MAX];
    __shared__ int  s_asup[AMB_MAX * 32];
    __shared__ int  s_keep_orig[MAXK];
    __shared__ int  s_namb, s_ktot, s_fkept;
    __shared__ float rs_[1024];
    __shared__ int   ri_[1024];

    int tid = threadIdx.x;
    int lane = tid & 31;
    int wi = tid >> 5;
    unsigned lt = (1u << lane) - 1u;

    int cnt_all = g_cnt;
    int n = cnt_all < CAP ? cnt_all : CAP;
    int j1 = tid, j2 = tid + 1024;              // slot ids

    // ---- suppressor counts -> kept init + ambiguous flags ----
    int c1 = (j1 < n) ? g_supcnt[j1] : 0;
    int c2 = (j2 < n) ? g_supcnt[j2] : 0;
    s_cnt[j1] = c1;
    s_cnt[j2] = c2;
    bool a1 = (j1 < n) && (c1 > 0);
    bool a2 = (j2 < n) && (c2 > 0);
    s_kept[j1] = ((j1 < n) && c1 == 0) ? 1 : 0;
    s_kept[j2] = ((j2 < n) && c2 == 0) ? 1 : 0;
    int ovf = __syncthreads_or((c1 > SUPK) || (c2 > SUPK));

    // ---- compact ambiguous slots (slot order) via ballot prefix-scan ----
    {
        unsigned b1 = __ballot_sync(FULLM, a1);
        unsigned b2 = __ballot_sync(FULLM, a2);
        if (lane == 0) { s_ab[wi] = b1; s_ab[32 + wi] = b2; }
    }
    __syncthreads();
    if (tid < 32) {
        int cA = __popc(s_ab[tid]);
        int cB = __popc(s_ab[tid + 32]);
        int sA = cA, sB = cB;
        #pragma unroll
        for (int o = 1; o < 32; o <<= 1) { int v = __shfl_up_sync(FULLM, sA, o); if (lane >= o) sA += v; }
        int totA = __shfl_sync(FULLM, sA, 31);
        #pragma unroll
        for (int o = 1; o < 32; o <<= 1) { int v = __shfl_up_sync(FULLM, sB, o); if (lane >= o) sB += v; }
        int totB = __shfl_sync(FULLM, sB, 31);
        s_awbase[tid] = sA - cA;
        s_awbase[tid + 32] = totA + sB - cB;
        if (tid == 0) s_namb = totA + totB;
    }
    __syncthreads();
    int namb = s_namb;

    if (a1) { int r = s_awbase[wi] + __popc(s_ab[wi] & lt); if (r < AMB_MAX) s_alist[r] = j1; }
    if (a2) { int r = s_awbase[32 + wi] + __popc(s_ab[32 + wi] & lt); if (r < AMB_MAX) s_alist[r] = j2; }
    __syncthreads();

    if (namb <= AMB_MAX) {
        // ---- reorder ambiguous slots by RANK (parallel rank-count) ----
        if (tid < namb) s_arank[tid] = g_rank[s_alist[tid]];
        __syncthreads();
        if (tid < namb) {
            int myr = s_arank[tid];
            int pos = 0;
            for (int b = 0; b < namb; b++) pos += (s_arank[b] < myr) ? 1 : 0;
            s_alist2[pos] = s_alist[tid];
        }
        __syncthreads();
        // ---- bulk preload suppressor entries ----
        for (int idx = tid; idx < namb * 32; idx += 1024) {
            int a = idx >> 5, l = idx & 31;
            int slot = s_alist2[a];
            int c = s_cnt[slot]; if (c > SUPK) c = SUPK;
            if (l < c) s_asup[idx] = g_suplist[slot * SUPK + l];
        }
        __syncthreads();
        // ---- tiny serial resolution in rank order ----
        if (tid == 0) {
            for (int a = 0; a < namb; a++) {
                int slot = s_alist2[a];
                int c = s_cnt[slot]; if (c > SUPK) c = SUPK;
                int k = 1;
                for (int l = 0; l < c; l++)
                    if (s_kept[s_asup[a * 32 + l]]) { k = 0; break; }
                s_kept[slot] = (unsigned char)k;
            }
        }
        __syncthreads();
    }

    // ---- kept flags by RANK; ranks via ballot prefix-scan ----
    int r1 = tid, r2 = tid + 1024;
    int slot1 = (r1 < n) ? g_slotofrank[r1] : 0;
    int slot2 = (r2 < n) ? g_slotofrank[r2] : 0;
    bool k1 = (r1 < n) && (s_kept[slot1] != 0);
    bool k2 = (r2 < n) && (s_kept[slot2] != 0);
    {
        unsigned b1 = __ballot_sync(FULLM, k1);
        unsigned b2 = __ballot_sync(FULLM, k2);
        if (lane == 0) { s_kb[wi] = b1; s_kb[32 + wi] = b2; }
    }
    __syncthreads();
    if (tid < 32) {
        int cA = __popc(s_kb[tid]);
        int cB = __popc(s_kb[tid + 32]);
        int sA = cA, sB = cB;
        #pragma unroll
        for (int o = 1; o < 32; o <<= 1) { int v = __shfl_up_sync(FULLM, sA, o); if (lane >= o) sA += v; }
        int totA = __shfl_sync(FULLM, sA, 31);
        #pragma unroll
        for (int o = 1; o < 32; o <<= 1) { int v = __shfl_up_sync(FULLM, sB, o); if (lane >= o) sB += v; }
        int totB = __shfl_sync(FULLM, sB, 31);
        s_wbase[tid] = sA - cA;
        s_wbase[tid + 32] = totA + sB - cB;
        if (tid == 0) s_ktot = totA + totB;
    }
    __syncthreads();
    int ktot = s_ktot;

    bool fb = ovf || (cnt_all > CAP) || (namb > AMB_MAX) || (ktot < MAXK);

    float thr = thrp[0];
    float* ob = out;                 // [750,4]
    float* os = out + MAXK * 4;      // [750]
    float* ol = out + MAXK * 5;      // [750,10]

    if (!fb) {
        // ---- FAST finalize: ktot >= 750 -> every out row written exactly once ----
        #pragma unroll
        for (int h = 0; h < 2; h++) {
            int r = (h == 0) ? r1 : r2;
            bool kp = (h == 0) ? k1 : k2;
            int slot = (h == 0) ? slot1 : slot2;
            if (kp) {
                int w = r >> 5;
                int pos = s_wbase[w] + __popc(s_kb[w] & lt);
                if (pos < MAXK) {
                    unsigned long long key = g_ckeys[slot];
                    int orig = (int)(0xFFFFFFFFu - (unsigned)(key & 0xFFFFFFFFull));
                    float sc = __uint_as_float((unsigned)(key >> 32));
                    if (sc > thr) {
                        float4 b = g_cbox[slot];
                        ob[4 * pos + 0] = b.x; ob[4 * pos + 1] = b.y;
                        ob[4 * pos + 2] = b.z; ob[4 * pos + 3] = b.w;
                        os[pos] = sc;
                        float px, py, ps;
                        get_prior(orig, px, py, ps);
                        #pragma unroll
                        for (int q = 0; q < 5; q++) {
                            float ox = landms[10 * orig + 2 * q + 0];
                            float oy = landms[10 * orig + 2 * q + 1];
                            ol[10 * pos + 2 * q + 0] = __fmul_rn(__fadd_rn(px, __fmul_rn(__fmul_rn(ox, 0.1f), ps)), 2560.0f);
                            ol[10 * pos + 2 * q + 1] = __fmul_rn(__fadd_rn(py, __fmul_rn(__fmul_rn(oy, 0.1f), ps)), 2560.0f);
                        }
                    } else {
                        ob[4 * pos + 0] = 0.f; ob[4 * pos + 1] = 0.f;
                        ob[4 * pos + 2] = 0.f; ob[4 * pos + 3] = 0.f;
                        os[pos] = 0.f;
                        #pragma unroll
                        for (int q = 0; q < 10; q++) ol[10 * pos + q] = 0.f;
                    }
                }
            }
        }
    } else {
        // ---- guaranteed-correct full reference fallback ----
        // Phase A: decode ALL boxes (single block; slow but never expected)
        for (int i = tid; i < N_PRIORS; i += 1024) {
            float px, py, ps;
            get_prior(i, px, py, ps);
            float4 l = reinterpret_cast<const float4*>(loc)[i];
            g_boxes[i] = decode_box(l, px, py, ps);
        }
        for (int w = tid; w < NSUPW; w += 1024) g_supp[w] = 0u;
        __syncthreads();

        int kept = 0;
        for (int it = 0; it < MAXK; it++) {
            float bs = -1.0f; int bi = 0x7FFFFFFF;
            for (int i = tid; i < N_PRIORS; i += 1024) {
                if (!((g_supp[i >> 5] >> (i & 31)) & 1u)) {
                    float s = scores[i];
                    if (s > bs || (s == bs && i < bi)) { bs = s; bi = i; }
                }
            }
            rs_[tid] = bs; ri_[tid] = bi;
            __syncthreads();
            for (int off = 512; off > 0; off >>= 1) {
                if (tid < off) {
                    float so = rs_[tid + off]; int io = ri_[tid + off];
                    if (so > rs_[tid] || (so == rs_[tid] && io < ri_[tid])) {
                        rs_[tid] = so; ri_[tid] = io;
                    }
                }
                __syncthreads();
            }
            float topS = rs_[0]; int top = ri_[0];
            __syncthreads();
            if (topS < 0.0f) break;

            if (tid == 0) s_keep_orig[kept] = top;
            kept++;

            float4 bt = g_boxes[top];
            float at = box_area(bt);
            for (int i = tid; i < N_PRIORS; i += 1024) {
                float4 bx = g_boxes[i];
                if (iou_gt(bt, at, bx, box_area(bx)))
                    atomicOr(&g_supp[i >> 5], 1u << (i & 31));
            }
            __syncthreads();
        }
        if (tid == 0) s_fkept = kept;
        __syncthreads();
        int fkept = s_fkept;

        if (tid < MAXK) {
            int i = tid;
            float4 b = make_float4(0.f, 0.f, 0.f, 0.f);
            float s = 0.f;
            float lm[10];
            #pragma unroll
            for (int q = 0; q < 10; q++) lm[q] = 0.f;

            if (i < fkept) {
                int orig = s_keep_orig[i];
                float sc = scores[orig];
                if (sc > thr) {
                    b = g_boxes[orig];
                    s = sc;
                    float px, py, ps;
                    get_prior(orig, px, py, ps);
                    #pragma unroll
                    for (int q = 0; q < 5; q++) {
                        float ox = landms[10 * orig + 2 * q + 0];
                        float oy = landms[10 * orig + 2 * q + 1];
                        lm[2 * q + 0] = __fmul_rn(__fadd_rn(px, __fmul_rn(__fmul_rn(ox, 0.1f), ps)), 2560.0f);
                        lm[2 * q + 1] = __fmul_rn(__fadd_rn(py, __fmul_rn(__fmul_rn(oy, 0.1f), ps)), 2560.0f);
                    }
                }
            }
            ob[4 * i + 0] = b.x; ob[4 * i + 1] = b.y;
            ob[4 * i + 2] = b.z; ob[4 * i + 3] = b.w;
            os[i] = s;
            #pragma unroll
            for (int q = 0; q < 10; q++) ol[10 * i + q] = lm[q];
        }
    }

    // ---- tail reset for next graph replay ----
    __syncthreads();
    g_supcnt[j1] = 0;
    g_supcnt[j2] = 0;
    if (tid == 0) g_cnt = 0;
}

// ---------------- launch ----------------
extern "C" void kernel_launch(void* const* d_in, const int* in_sizes, int n_in,
                              void* d_out, int out_size) {
    const float* bboxes = (const float*)d_in[0];   // (1, N, 4)
    const float* scores = (const float*)d_in[1];   // (1, N)
    const float* landms = (const float*)d_in[2];   // (1, N, 10)
    const float* thr    = (const float*)d_in[3];   // (1,)
    float* out = (float*)d_out;
    cudaStream_t stream = 0;

    decode_kernel<<<N_PRIORS / 256, 256, 0, stream>>>(bboxes, scores);
    ranksup_kernel<<<8 + 256, 256, 0, stream>>>();
    resolve_kernel<<<1, 1024, 0, stream>>>(bboxes, scores, landms, thr, out);
}